// round 10
// baseline (speedup 1.0000x reference)
#include <cuda_runtime.h>
#include <cstdint>

#define N_NODES    200000
#define N_CHILD    32
#define N_LAYERS   8
#define N_CHUNKS   4
#define CHUNK      50000          // floats per chunk: 200KB smem; 4*50000=200000
#define N_RANGES   37
#define RANGE_SZ   5408           // 37*5408 >= 200000, multiple of 8
#define THREADS    1024

// Ping-pong layer-value buffers (src/dst distinct — no grid sync in a launch).
__device__ float g_bufA[N_NODES];
__device__ float g_bufB[N_NODES];
// Partials transposed: one float4 per node, component c = chunk-c partial.
__device__ float4 g_partial4[N_NODES];
// Monotonic arrival counters (replay-safe via mod-4; zero-init at load).
__device__ unsigned g_arrive[N_RANGES];

// Grid = 37 ranges x 4 chunks = 148 blocks, free scheduling (NO clusters).
// Block (range,chunk): stages its 50K-float chunk to smem, computes chunk-c
// partial sums for all nodes of its range via predicated LDS (fast crossbar),
// stores each into component c of g_partial4[node], then fence + atomicAdd
// on the range counter. The 4th arriver combines the range with ONE float4
// load per node: w*sum + activation -> dst. Deterministic values (fixed
// chunk->component map; all partials complete before the 4th arrival).
__global__ void __launch_bounds__(THREADS, 1) layer_kernel(
    const float* __restrict__ src,     // previous layer values [N_NODES]
    float*       __restrict__ dst,     // this layer's outputs   [N_NODES]
    const int4*  __restrict__ cidx,    // this layer's indices as int4
    const int*   __restrict__ fids,    // this layer's fun_ids
    const float* __restrict__ wptr)
{
    extern __shared__ float sval[];    // CHUNK floats

    const int chunk = blockIdx.x & (N_CHUNKS - 1);
    const int range = blockIdx.x >> 2;
    const int cbase = chunk * CHUNK;
    const int range_start = range * RANGE_SZ;

    // ---- Phase 1: stage chunk (coalesced float4; src is L2-resident) ----
    {
        const float4* s4 = (const float4*)(src + cbase);
        float4* d4 = (float4*)sval;
        #pragma unroll 4
        for (int i = threadIdx.x; i < CHUNK / 4; i += THREADS)
            d4[i] = s4[i];
    }
    __syncthreads();

    // ---- Phase 2: chunk-c partial sums (R4's proven simple loop) ----
    const int warp = threadIdx.x >> 5;
    const int lane = threadIdx.x & 31;

    for (int t = warp; t * 8 < RANGE_SZ; t += THREADS / 32) {
        const int node0 = range_start + t * 8;
        if (node0 >= N_NODES) break;

        const size_t ibase = (size_t)node0 * (N_CHILD / 4);
        const int4 cA = cidx[ibase + lane];
        const int4 cB = cidx[ibase + 32 + lane];

        float sA = 0.0f, sB = 0.0f;
        {
            unsigned r;
            r = (unsigned)(cA.x - cbase); if (r < CHUNK) sA += sval[r];
            r = (unsigned)(cA.y - cbase); if (r < CHUNK) sA += sval[r];
            r = (unsigned)(cA.z - cbase); if (r < CHUNK) sA += sval[r];
            r = (unsigned)(cA.w - cbase); if (r < CHUNK) sA += sval[r];
            r = (unsigned)(cB.x - cbase); if (r < CHUNK) sB += sval[r];
            r = (unsigned)(cB.y - cbase); if (r < CHUNK) sB += sval[r];
            r = (unsigned)(cB.z - cbase); if (r < CHUNK) sB += sval[r];
            r = (unsigned)(cB.w - cbase); if (r < CHUNK) sB += sval[r];
        }

        sA += __shfl_down_sync(0xffffffffu, sA, 4);
        sB += __shfl_down_sync(0xffffffffu, sB, 4);
        sA += __shfl_down_sync(0xffffffffu, sA, 2);
        sB += __shfl_down_sync(0xffffffffu, sB, 2);
        sA += __shfl_down_sync(0xffffffffu, sA, 1);
        sB += __shfl_down_sync(0xffffffffu, sB, 1);

        if ((lane & 7) == 0) {
            const int g = lane >> 3;
            ((float*)&g_partial4[node0 + g])[chunk]     = sA;
            ((float*)&g_partial4[node0 + 4 + g])[chunk] = sB;
        }
    }

    // ---- Phase 3: publish partials, count arrivals ----
    __threadfence();        // partial stores visible gpu-wide
    __syncthreads();        // all threads' stores fenced before arrival

    __shared__ int s_combine;
    if (threadIdx.x == 0) {
        const unsigned old = atomicAdd(&g_arrive[range], 1u);
        s_combine = ((old & 3u) == 3u) ? 1 : 0;
    }
    __syncthreads();

    // ---- Phase 4: 4th arriver combines this range (float4 per node) ----
    if (s_combine) {
        __threadfence();    // acquire: see peers' partial stores
        const float wv = *wptr;
        for (int i = threadIdx.x; i < RANGE_SZ; i += THREADS) {
            const int n = range_start + i;
            if (n >= N_NODES) break;
            const float4 p = g_partial4[n];
            const float s = (p.x + p.y) + (p.z + p.w);
            const float x = wv * s;
            const int fid = __ldg(fids + n);
            float r;
            if      (fid == 0) r = tanhf(x);
            else if (fid == 1) r = 1.0f / (1.0f + expf(-x));
            else if (fid == 2) r = fmaxf(x, 0.0f);
            else               r = x;
            dst[n] = r;
        }
    }
}

extern "C" void kernel_launch(void* const* d_in, const int* in_sizes, int n_in,
                              void* d_out, int out_size)
{
    const float* X    = (const float*)d_in[0];
    const float* w    = (const float*)d_in[1];
    const int*   cidx = (const int*)  d_in[2];  // [N_LAYERS, N_NODES, N_CHILD]
    const int*   fids = (const int*)  d_in[3];  // [N_LAYERS, N_NODES]
    float*       out  = (float*)d_out;

    float* bufA = nullptr;
    float* bufB = nullptr;
    cudaGetSymbolAddress((void**)&bufA, g_bufA);
    cudaGetSymbolAddress((void**)&bufB, g_bufB);

    const size_t SMEM_BYTES = (size_t)CHUNK * sizeof(float);  // 200KB
    cudaFuncSetAttribute(layer_kernel,
                         cudaFuncAttributeMaxDynamicSharedMemorySize,
                         (int)SMEM_BYTES);

    // Ping-pong: layer i reads ins[i], writes outs[i] (always distinct).
    const float* ins[N_LAYERS]  = { X, bufA, bufB, bufA, bufB, bufA, bufB, bufA };
    float*       outs[N_LAYERS] = { bufA, bufB, bufA, bufB, bufA, bufB, bufA, out };

    const int grid = N_RANGES * N_CHUNKS;   // 148 blocks, one wave

    for (int l = 0; l < N_LAYERS; l++) {
        const int4* layer_cidx =
            (const int4*)(cidx + (size_t)l * N_NODES * N_CHILD);
        const int* layer_fids = fids + (size_t)l * N_NODES;

        layer_kernel<<<grid, THREADS, SMEM_BYTES>>>(
            ins[l], outs[l], layer_cidx, layer_fids, w);
    }
}

// round 11
// speedup vs baseline: 1.6734x; 1.6734x over previous
#include <cuda_runtime.h>
#include <cstdint>

#define N_NODES    200000
#define N_CHILD    32
#define N_LAYERS   8
#define N_CHUNKS   4
#define CHUNK      50000          // floats per chunk: 200KB smem; 4*50000=200000
#define N_RANGES   37
#define RANGE_SZ   5408           // 37*5408 >= 200000, multiple of 8
#define THREADS    1024

// Ping-pong layer-value buffers (src/dst distinct — no grid sync in a launch).
__device__ float g_bufA[N_NODES];
__device__ float g_bufB[N_NODES];
// Per-chunk partial arrays: contiguous, single-writer cache lines.
// (Do NOT transpose into float4-per-node: 4 SMs interleaving 4B component
// stores into shared 16B slots cost ~+18us/layer in R10.)
__device__ float g_partial[N_CHUNKS][N_NODES];

// ---------------- Gather (verbatim R4 — proven 18.6us/layer) ----------------
// Grid = 37 ranges x 4 chunks = 148 blocks. Block (range,chunk) stages its
// 50K-float chunk into smem, then computes the chunk's partial sum for every
// node in its range via predicated LDS (fast crossbar) and writes
// g_partial[chunk][node]. 8 nodes/warp-task via two int4 loads per lane;
// 8-lane shfl groups reduce each node.
__global__ void __launch_bounds__(THREADS, 1) gather_kernel(
    const float* __restrict__ src,     // layer-input values [N_NODES]
    const int4*  __restrict__ cidx)    // this layer's indices as int4
{
    extern __shared__ float sval[];    // CHUNK floats

    const int chunk = blockIdx.x & (N_CHUNKS - 1);
    const int range = blockIdx.x >> 2;
    const int cbase = chunk * CHUNK;

    {
        const float4* s4 = (const float4*)(src + cbase);
        float4* d4 = (float4*)sval;
        for (int i = threadIdx.x; i < CHUNK / 4; i += THREADS)
            d4[i] = s4[i];
    }
    __syncthreads();

    const int warp = threadIdx.x >> 5;
    const int lane = threadIdx.x & 31;
    const int range_start = range * RANGE_SZ;

    for (int t = warp; t * 8 < RANGE_SZ; t += THREADS / 32) {
        const int node0 = range_start + t * 8;
        if (node0 >= N_NODES) break;

        const size_t ibase = (size_t)node0 * (N_CHILD / 4);
        const int4 cA = cidx[ibase + lane];
        const int4 cB = cidx[ibase + 32 + lane];

        float sA = 0.0f, sB = 0.0f;
        {
            unsigned r;
            r = (unsigned)(cA.x - cbase); if (r < CHUNK) sA += sval[r];
            r = (unsigned)(cA.y - cbase); if (r < CHUNK) sA += sval[r];
            r = (unsigned)(cA.z - cbase); if (r < CHUNK) sA += sval[r];
            r = (unsigned)(cA.w - cbase); if (r < CHUNK) sA += sval[r];
            r = (unsigned)(cB.x - cbase); if (r < CHUNK) sB += sval[r];
            r = (unsigned)(cB.y - cbase); if (r < CHUNK) sB += sval[r];
            r = (unsigned)(cB.z - cbase); if (r < CHUNK) sB += sval[r];
            r = (unsigned)(cB.w - cbase); if (r < CHUNK) sB += sval[r];
        }

        sA += __shfl_down_sync(0xffffffffu, sA, 4);
        sB += __shfl_down_sync(0xffffffffu, sB, 4);
        sA += __shfl_down_sync(0xffffffffu, sA, 2);
        sB += __shfl_down_sync(0xffffffffu, sB, 2);
        sA += __shfl_down_sync(0xffffffffu, sA, 1);
        sB += __shfl_down_sync(0xffffffffu, sB, 1);

        if ((lane & 7) == 0) {
            const int g = lane >> 3;
            g_partial[chunk][node0 + g]     = sA;
            g_partial[chunk][node0 + 4 + g] = sB;
        }
    }
}

// ---------------- Combine (vectorized: 4 consecutive nodes/thread) ----------
// Thread t handles nodes 4t..4t+3: one float4 load from each of the 4 partial
// arrays (coalesced LDG.128, 4-deep MLP), one int4 fids load, one float4
// store. Same bytes as before, ~2x less exposed latency.
__global__ void __launch_bounds__(512) combine_kernel(
    float*       __restrict__ dst,
    const int*   __restrict__ fids,    // this layer's fun_ids
    const float* __restrict__ wptr)
{
    const int t = blockIdx.x * blockDim.x + threadIdx.x;
    const int n0 = t * 4;
    if (n0 >= N_NODES) return;          // N_NODES % 4 == 0: full quads only

    const float4 p0 = *(const float4*)&g_partial[0][n0];
    const float4 p1 = *(const float4*)&g_partial[1][n0];
    const float4 p2 = *(const float4*)&g_partial[2][n0];
    const float4 p3 = *(const float4*)&g_partial[3][n0];
    const int4   f  = *(const int4*)(fids + n0);
    const float wv = *wptr;

    float s[4] = { (p0.x + p1.x) + (p2.x + p3.x),
                   (p0.y + p1.y) + (p2.y + p3.y),
                   (p0.z + p1.z) + (p2.z + p3.z),
                   (p0.w + p1.w) + (p2.w + p3.w) };
    const int fid[4] = { f.x, f.y, f.z, f.w };

    float4 o;
    float* op = (float*)&o;
    #pragma unroll
    for (int k = 0; k < 4; k++) {
        const float x = wv * s[k];
        float r;
        if      (fid[k] == 0) r = tanhf(x);
        else if (fid[k] == 1) r = 1.0f / (1.0f + expf(-x));
        else if (fid[k] == 2) r = fmaxf(x, 0.0f);
        else                  r = x;
        op[k] = r;
    }
    *(float4*)(dst + n0) = o;
}

extern "C" void kernel_launch(void* const* d_in, const int* in_sizes, int n_in,
                              void* d_out, int out_size)
{
    const float* X    = (const float*)d_in[0];
    const float* w    = (const float*)d_in[1];
    const int*   cidx = (const int*)  d_in[2];  // [N_LAYERS, N_NODES, N_CHILD]
    const int*   fids = (const int*)  d_in[3];  // [N_LAYERS, N_NODES]
    float*       out  = (float*)d_out;

    float* bufA = nullptr;
    float* bufB = nullptr;
    cudaGetSymbolAddress((void**)&bufA, g_bufA);
    cudaGetSymbolAddress((void**)&bufB, g_bufB);

    const size_t SMEM_BYTES = (size_t)CHUNK * sizeof(float);  // 200KB
    cudaFuncSetAttribute(gather_kernel,
                         cudaFuncAttributeMaxDynamicSharedMemorySize,
                         (int)SMEM_BYTES);

    // Ping-pong: layer i reads ins[i], writes outs[i] (always distinct).
    const float* ins[N_LAYERS]  = { X, bufA, bufB, bufA, bufB, bufA, bufB, bufA };
    float*       outs[N_LAYERS] = { bufA, bufB, bufA, bufB, bufA, bufB, bufA, out };

    const int gather_grid  = N_RANGES * N_CHUNKS;            // 148
    const int combine_grid = (N_NODES / 4 + 511) / 512;      // 98

    for (int l = 0; l < N_LAYERS; l++) {
        const int4* layer_cidx =
            (const int4*)(cidx + (size_t)l * N_NODES * N_CHILD);
        const int* layer_fids = fids + (size_t)l * N_NODES;

        gather_kernel<<<gather_grid, THREADS, SMEM_BYTES>>>(ins[l], layer_cidx);
        combine_kernel<<<combine_grid, 512>>>(outs[l], layer_fids, w);
    }
}